// round 10
// baseline (speedup 1.0000x reference)
#include <cuda_runtime.h>
#include <cuda_bf16.h>
#include <stdint.h>
#include <math.h>

#define NN 8192
#define DD 512
#define SCALE 0.044194173824159216f

// ----------------- device scratch (allocation-free rule), all fp32/tf32 ----
__device__ float gx[NN * DD];          // x rounded to tf32
__device__ float gw[3 * DD * DD];      // Wq/Wk/Wv rounded to tf32
__device__ float g_q[NN * DD];         // Q (tf32-rounded)
__device__ float g_k[NN * DD];         // K (tf32-rounded)
__device__ float g_v[NN * DD];         // V (full fp32; rounded at vtrans)
__device__ float g_vt[DD * NN];        // V^T (tf32-rounded)
__device__ float g_P[(size_t)NN * NN]; // P (tf32-rounded)
__device__ float g_lpart[64 * NN];
__device__ float g_l[NN];

// ----------------- helpers -----------------
__device__ __forceinline__ uint32_t smem_u32(const void* p) {
    uint32_t a;
    asm("{ .reg .u64 t; cvta.to.shared.u64 t, %1; cvt.u32.u64 %0, t; }" : "=r"(a) : "l"(p));
    return a;
}
__device__ __forceinline__ float tf32r(float x) {
    uint32_t u;
    asm("cvt.rna.tf32.f32 %0, %1;" : "=r"(u) : "f"(x));
    return __uint_as_float(u);
}
__device__ __forceinline__ void cpa16(uint32_t dst, const void* src) {
    asm volatile("cp.async.cg.shared.global [%0], [%1], 16;" :: "r"(dst), "l"(src));
}
__device__ __forceinline__ void cpa_commit() {
    asm volatile("cp.async.commit_group;" ::: "memory");
}
__device__ __forceinline__ void ldsm4(uint32_t* r, uint32_t addr) {
    asm volatile("ldmatrix.sync.aligned.m8n8.x4.shared.b16 {%0,%1,%2,%3}, [%4];"
                 : "=r"(r[0]), "=r"(r[1]), "=r"(r[2]), "=r"(r[3]) : "r"(addr));
}
__device__ __forceinline__ void mma_tf32(float* c, const uint32_t* a, const uint32_t* b) {
    asm volatile(
        "mma.sync.aligned.m16n8k8.row.col.f32.tf32.tf32.f32 "
        "{%0,%1,%2,%3}, {%4,%5,%6,%7}, {%8,%9}, {%0,%1,%2,%3};"
        : "+f"(c[0]), "+f"(c[1]), "+f"(c[2]), "+f"(c[3])
        : "r"(a[0]), "r"(a[1]), "r"(a[2]), "r"(a[3]), "r"(b[0]), "r"(b[1]));
}

// ---------------------------------------------------------------------------
// Round x and Wq/Wk/Wv to tf32 (rna)
// ---------------------------------------------------------------------------
__global__ __launch_bounds__(256)
void round_kernel(const float* __restrict__ x, const float* __restrict__ Wq,
                  const float* __restrict__ Wk, const float* __restrict__ Wv) {
    int i4 = blockIdx.x * 256 + threadIdx.x;
    const float4* src;
    float4* dst;
    int off;
    if (i4 < NN * DD / 4) {
        src = (const float4*)x; dst = (float4*)gx; off = i4;
    } else {
        int r = i4 - NN * DD / 4;
        int wi = r >> 16, rr = r & 65535;
        const float* w = (wi == 0) ? Wq : (wi == 1) ? Wk : Wv;
        src = (const float4*)w; off = rr;
        dst = (float4*)(gw + (size_t)wi * DD * DD);
    }
    float4 v = src[off];
    dst[off] = make_float4(tf32r(v.x), tf32r(v.y), tf32r(v.z), tf32r(v.w));
}

// ---------------------------------------------------------------------------
// TF32 GEMM body: CTA 128x128, warps 2x4, warp 64x32, K-chunk 32 fp32.
// Stage per buffer (36864B): A (128 rows x 144B) @0, B @18432.
// ---------------------------------------------------------------------------
#define STG32 36864

#define STAGE32(A, B, cc, buf, LDA)                                               \
    {                                                                             \
        int kk_ = (cc) * 32;                                                      \
        uint32_t d_ = sb + (buf) * STG32;                                         \
        const float* a_ = (A) + (size_t)m0 * (LDA) + kk_;                         \
        const float* b_ = (B) + (size_t)n0 * (LDA) + kk_;                         \
        _Pragma("unroll")                                                         \
        for (int i_ = 0; i_ < 4; ++i_) {                                          \
            int idx_ = t + i_ * 256;                                              \
            int r_ = idx_ >> 3, ch_ = idx_ & 7;                                   \
            uint32_t ro_ = r_ * 144 + ch_ * 16;                                   \
            size_t go_ = (size_t)r_ * (LDA) + ch_ * 4;                            \
            cpa16(d_ + ro_, a_ + go_);                                            \
            cpa16(d_ + 18432 + ro_, b_ + go_);                                    \
        }                                                                         \
        cpa_commit();                                                             \
    }

#define COMPUTE32(buf)                                                            \
    {                                                                             \
        uint32_t sA = sb + (buf) * STG32, sB = sA + 18432;                        \
        _Pragma("unroll")                                                         \
        for (int s = 0; s < 4; ++s) {                                             \
            uint32_t b01[8];                                                      \
            ldsm4(b01 + 0, sB + bOff + s * 32);                                   \
            ldsm4(b01 + 4, sB + bOff + 2304 + s * 32);                            \
            _Pragma("unroll")                                                     \
            for (int mi = 0; mi < 4; ++mi) {                                      \
                uint32_t a[4];                                                    \
                ldsm4(a, sA + aOff + mi * 2304 + s * 32);                         \
                _Pragma("unroll")                                                 \
                for (int nj = 0; nj < 4; ++nj)                                    \
                    mma_tf32(acc[mi][nj], a, b01 + nj * 2);                       \
            }                                                                     \
        }                                                                         \
    }

#define GEMM_PRO()                                                                \
    float acc[4][4][4];                                                           \
    _Pragma("unroll")                                                             \
    for (int mi = 0; mi < 4; ++mi)                                                \
        _Pragma("unroll")                                                         \
        for (int ni = 0; ni < 4; ++ni)                                            \
            _Pragma("unroll")                                                     \
            for (int q = 0; q < 4; ++q) acc[mi][ni][q] = 0.0f;                    \
    const uint32_t aOff = (uint32_t)(wr * 64 + (lane & 15)) * 144 + (lane >> 4) * 16; \
    const uint32_t bOff = (uint32_t)(wc * 32 + (lane & 7) + (lane >> 4) * 8) * 144 +  \
                          ((lane >> 3) & 1) * 16;

#define GEMM_LOOP(A, B, NC, LDA)                                                  \
    STAGE32(A, B, 0, 0, LDA);                                                     \
    for (int cc = 0; cc < (NC); ++cc) {                                           \
        asm volatile("cp.async.wait_group 0;" ::: "memory");                      \
        __syncthreads();                                                          \
        if (cc < (NC) - 1) STAGE32(A, B, cc + 1, (cc + 1) & 1, LDA);              \
        COMPUTE32(cc & 1);                                                        \
    }

// ---------------------------------------------------------------------------
// QKV projection (tf32). z=0:Q, z=1:K (tf32-rounded out), z=2:V (fp32 out).
// ---------------------------------------------------------------------------
__global__ __launch_bounds__(256, 2)
void proj_kernel(const float* __restrict__ bq, const float* __restrict__ bk,
                 const float* __restrict__ bv) {
    extern __shared__ __align__(128) char smem[];
    const int t = threadIdx.x, wid = t >> 5, lane = t & 31;
    const int z = blockIdx.z;
    const int m0 = blockIdx.y * 128, n0 = blockIdx.x * 128;
    const uint32_t sb = smem_u32(smem);
    const int wr = wid >> 2, wc = wid & 3;
    const float* Wz = gw + (size_t)z * DD * DD;

    GEMM_PRO();
    GEMM_LOOP(gx, Wz, 16, DD);

    const float* bias = (z == 0) ? bq : (z == 1) ? bk : bv;
    float* outp = (z == 0) ? g_q : (z == 1) ? g_k : g_v;
#pragma unroll
    for (int mi = 0; mi < 4; ++mi) {
#pragma unroll
        for (int h = 0; h < 2; ++h) {
            int row = m0 + wr * 64 + mi * 16 + (lane >> 2) + h * 8;
#pragma unroll
            for (int ni = 0; ni < 4; ++ni) {
                int col = n0 + wc * 32 + ni * 8 + (lane & 3) * 2;
                float2 bb = *(const float2*)(bias + col);
                float v0 = acc[mi][ni][h * 2] + bb.x;
                float v1 = acc[mi][ni][h * 2 + 1] + bb.y;
                if (z != 2) { v0 = tf32r(v0); v1 = tf32r(v1); }
                *(float2*)(outp + (size_t)row * DD + col) = make_float2(v0, v1);
            }
        }
    }
}

// ---------------------------------------------------------------------------
// V transpose + tf32 round: g_vt[d][j] = rna(g_v[j][d])
// ---------------------------------------------------------------------------
__global__ __launch_bounds__(256, 4)
void vtrans_kernel() {
    __shared__ float ts[32][33];
    int j0 = blockIdx.x * 32, d0 = blockIdx.y * 32;
    int tx = threadIdx.x & 31, ty = threadIdx.x >> 5;
#pragma unroll
    for (int i = 0; i < 4; ++i)
        ts[ty + 8 * i][tx] = g_v[(size_t)(j0 + ty + 8 * i) * DD + d0 + tx];
    __syncthreads();
#pragma unroll
    for (int i = 0; i < 4; ++i) {
        float v = ts[tx][ty + 8 * i];
        g_vt[(size_t)(d0 + ty + 8 * i) * NN + j0 + tx] = tf32r(v);
    }
}

// ---------------------------------------------------------------------------
// Pass 1: P = exp(scale*Q@K^T + sp + ed) (tf32 GEMM), store tf32-rounded P,
// per-CTA row-sum partials.
// ---------------------------------------------------------------------------
__global__ __launch_bounds__(256, 2)
void pass1_kernel(const float* __restrict__ sp, const float* __restrict__ ed) {
    extern __shared__ __align__(128) char smem[];
    float* smem_l = (float*)(smem + 2 * STG32);
    const int t = threadIdx.x, wid = t >> 5, lane = t & 31;
    const int m0 = blockIdx.y * 128, n0 = blockIdx.x * 128;
    const uint32_t sb = smem_u32(smem);
    const int wr = wid >> 2, wc = wid & 3;

    GEMM_PRO();
    GEMM_LOOP(g_q, g_k, 16, DD);

    // epilogue: bias add, exp, store P (tf32), row sums
#pragma unroll
    for (int mi = 0; mi < 4; ++mi) {
#pragma unroll
        for (int h = 0; h < 2; ++h) {
            int rloc = wr * 64 + mi * 16 + (lane >> 2) + h * 8;
            size_t rb = (size_t)(m0 + rloc) * NN;
            float rs = 0.0f;
#pragma unroll
            for (int ni = 0; ni < 4; ++ni) {
                int col = n0 + wc * 32 + ni * 8 + (lane & 3) * 2;
                float2 s2 = *(const float2*)(sp + rb + col);
                float2 e2 = *(const float2*)(ed + rb + col);
                float p0 = __expf(acc[mi][ni][h * 2] * SCALE + s2.x + e2.x);
                float p1 = __expf(acc[mi][ni][h * 2 + 1] * SCALE + s2.y + e2.y);
                *(float2*)(g_P + rb + col) = make_float2(tf32r(p0), tf32r(p1));
                rs += p0 + p1;
            }
            rs += __shfl_xor_sync(0xffffffffu, rs, 1);
            rs += __shfl_xor_sync(0xffffffffu, rs, 2);
            if ((lane & 3) == 0) smem_l[rloc * 4 + wc] = rs;
        }
    }
    __syncthreads();
    if (t < 128) {
        float s = smem_l[t * 4] + smem_l[t * 4 + 1] + smem_l[t * 4 + 2] + smem_l[t * 4 + 3];
        g_lpart[(size_t)blockIdx.x * NN + m0 + t] = s;
    }
}

// ---------------------------------------------------------------------------
// l reduce (deterministic)
// ---------------------------------------------------------------------------
__global__ void lreduce_kernel() {
    int r = blockIdx.x * 256 + threadIdx.x;
    float s = 0.0f;
    for (int b = 0; b < 64; ++b) s += g_lpart[(size_t)b * NN + r];
    g_l[r] = s;
}

// ---------------------------------------------------------------------------
// Pass 2: O = (P @ V) / l (tf32 GEMM). CTA 128x128 (m x d), K=8192, 256 chunks.
// ---------------------------------------------------------------------------
__global__ __launch_bounds__(256, 2)
void pass2_kernel(float* __restrict__ outp) {
    extern __shared__ __align__(128) char smem[];
    const int t = threadIdx.x, wid = t >> 5, lane = t & 31;
    const int n0 = blockIdx.x * 128, m0 = blockIdx.y * 128;
    const uint32_t sb = smem_u32(smem);
    const int wr = wid >> 2, wc = wid & 3;

    GEMM_PRO();
    GEMM_LOOP(g_P, g_vt, 256, NN);

    // epilogue: divide by l, store
#pragma unroll
    for (int mi = 0; mi < 4; ++mi) {
#pragma unroll
        for (int h = 0; h < 2; ++h) {
            int row = m0 + wr * 64 + mi * 16 + (lane >> 2) + h * 8;
            float inv = 1.0f / g_l[row];
#pragma unroll
            for (int ni = 0; ni < 4; ++ni) {
                int col = n0 + wc * 32 + ni * 8 + (lane & 3) * 2;
                float2 o;
                o.x = acc[mi][ni][h * 2] * inv;
                o.y = acc[mi][ni][h * 2 + 1] * inv;
                *(float2*)(outp + (size_t)row * DD + col) = o;
            }
        }
    }
}

// ---------------------------------------------------------------------------
extern "C" void kernel_launch(void* const* d_in, const int* in_sizes, int n_in,
                              void* d_out, int out_size) {
    const float* x       = (const float*)d_in[0];
    const float* spatial = (const float*)d_in[1];
    const float* edge    = (const float*)d_in[2];
    const float* Wq      = (const float*)d_in[3];
    const float* bq      = (const float*)d_in[4];
    const float* Wk      = (const float*)d_in[5];
    const float* bk      = (const float*)d_in[6];
    const float* Wv      = (const float*)d_in[7];
    const float* bv      = (const float*)d_in[8];
    float* out           = (float*)d_out;

    const int smem_main  = 2 * STG32;          // 73728
    const int smem_pass1 = 2 * STG32 + 2048;   // 75776

    cudaFuncSetAttribute(proj_kernel, cudaFuncAttributeMaxDynamicSharedMemorySize, smem_main);
    cudaFuncSetAttribute(pass1_kernel, cudaFuncAttributeMaxDynamicSharedMemorySize, smem_pass1);
    cudaFuncSetAttribute(pass2_kernel, cudaFuncAttributeMaxDynamicSharedMemorySize, smem_main);

    round_kernel<<<4864, 256>>>(x, Wq, Wk, Wv);
    proj_kernel<<<dim3(4, 64, 3), 256, smem_main>>>(bq, bk, bv);
    vtrans_kernel<<<dim3(NN / 32, DD / 32), 256>>>();
    pass1_kernel<<<dim3(64, 64), 256, smem_pass1>>>(spatial, edge);
    lreduce_kernel<<<32, 256>>>();
    pass2_kernel<<<dim3(4, 64), 256, smem_main>>>(out);
}

// round 14
// speedup vs baseline: 1.5014x; 1.5014x over previous
#include <cuda_runtime.h>
#include <cuda_bf16.h>
#include <cuda_fp16.h>
#include <stdint.h>
#include <math.h>

#define NN 8192
#define DD 512
#define SCALE 0.044194173824159216f
#define PSC 1.52587890625e-05f   // 2^-16
#define PSCI 65536.0f

// ----------------- device scratch (allocation-free rule) -----------------
__device__ float g_v[NN * DD];
__device__ __nv_bfloat16 gx_hi[NN * DD], gx_lo[NN * DD];
__device__ __nv_bfloat16 gw_hi[3 * DD * DD], gw_lo[3 * DD * DD];
__device__ __half gq_h[NN * DD], gq_l[NN * DD];   // Q fp16 hi/lo
__device__ __half gk_h[NN * DD];                  // K fp16 single
__device__ __half gvt_h[DD * NN];                 // V^T fp16 single
__device__ __half gP_h[(size_t)NN * NN], gP_l[(size_t)NN * NN];  // scaled P
__device__ float g_lpart[64 * NN];
__device__ float g_l[NN];

// ----------------- helpers -----------------
__device__ __forceinline__ uint32_t smem_u32(const void* p) {
    uint32_t a;
    asm("{ .reg .u64 t; cvta.to.shared.u64 t, %1; cvt.u32.u64 %0, t; }" : "=r"(a) : "l"(p));
    return a;
}
__device__ __forceinline__ uint32_t pack2(__nv_bfloat16 a, __nv_bfloat16 b) {
    return (uint32_t)__bfloat16_as_ushort(a) | ((uint32_t)__bfloat16_as_ushort(b) << 16);
}
__device__ __forceinline__ uint32_t pack2h(__half a, __half b) {
    return (uint32_t)__half_as_ushort(a) | ((uint32_t)__half_as_ushort(b) << 16);
}
__device__ __forceinline__ void cpa16(uint32_t dst, const void* src) {
    asm volatile("cp.async.cg.shared.global [%0], [%1], 16;" :: "r"(dst), "l"(src));
}
__device__ __forceinline__ void cpa_commit() {
    asm volatile("cp.async.commit_group;" ::: "memory");
}
__device__ __forceinline__ void ldsm4(uint32_t* r, uint32_t addr) {
    asm volatile("ldmatrix.sync.aligned.m8n8.x4.shared.b16 {%0,%1,%2,%3}, [%4];"
                 : "=r"(r[0]), "=r"(r[1]), "=r"(r[2]), "=r"(r[3]) : "r"(addr));
}
__device__ __forceinline__ void mma16816(float* c, const uint32_t* a, const uint32_t* b) {
    asm volatile(
        "mma.sync.aligned.m16n8k16.row.col.f32.bf16.bf16.f32 "
        "{%0,%1,%2,%3}, {%4,%5,%6,%7}, {%8,%9}, {%0,%1,%2,%3};"
        : "+f"(c[0]), "+f"(c[1]), "+f"(c[2]), "+f"(c[3])
        : "r"(a[0]), "r"(a[1]), "r"(a[2]), "r"(a[3]), "r"(b[0]), "r"(b[1]));
}
__device__ __forceinline__ void mma_h(float* c, const uint32_t* a, const uint32_t* b) {
    asm volatile(
        "mma.sync.aligned.m16n8k16.row.col.f32.f16.f16.f32 "
        "{%0,%1,%2,%3}, {%4,%5,%6,%7}, {%8,%9}, {%0,%1,%2,%3};"
        : "+f"(c[0]), "+f"(c[1]), "+f"(c[2]), "+f"(c[3])
        : "r"(a[0]), "r"(a[1]), "r"(a[2]), "r"(a[3]), "r"(b[0]), "r"(b[1]));
}

// ---------------------------------------------------------------------------
// Split x and Wq/Wk/Wv into bf16 hi/lo (proj inputs; fp32-accurate 3-term)
// ---------------------------------------------------------------------------
__global__ __launch_bounds__(256)
void split_kernel(const float* __restrict__ x, const float* __restrict__ Wq,
                  const float* __restrict__ Wk, const float* __restrict__ Wv) {
    int i4 = blockIdx.x * 256 + threadIdx.x;
    const float4* src;
    uint2 *oh, *ol;
    int off;
    if (i4 < NN * DD / 4) {
        src = (const float4*)x; oh = (uint2*)gx_hi; ol = (uint2*)gx_lo; off = i4;
    } else {
        int r = i4 - NN * DD / 4;
        int wi = r >> 16, rr = r & 65535;
        const float* w = (wi == 0) ? Wq : (wi == 1) ? Wk : Wv;
        src = (const float4*)w; off = rr;
        oh = (uint2*)(gw_hi + (size_t)wi * DD * DD);
        ol = (uint2*)(gw_lo + (size_t)wi * DD * DD);
    }
    float4 v = src[off];
    __nv_bfloat16 h0 = __float2bfloat16(v.x), h1 = __float2bfloat16(v.y);
    __nv_bfloat16 h2 = __float2bfloat16(v.z), h3 = __float2bfloat16(v.w);
    uint2 H, L;
    H.x = pack2(h0, h1);
    H.y = pack2(h2, h3);
    L.x = pack2(__float2bfloat16(v.x - __bfloat162float(h0)),
                __float2bfloat16(v.y - __bfloat162float(h1)));
    L.y = pack2(__float2bfloat16(v.z - __bfloat162float(h2)),
                __float2bfloat16(v.w - __bfloat162float(h3)));
    oh[off] = H;
    ol[off] = L;
}

// ---------------------------------------------------------------------------
// 3-term bf16 GEMM body for proj (CTA 128x128, warps 2x4, warp 64x32).
// Stage per buffer (40960B): Ah@0, Al@10240, Bh@20480, Bl@30720.
// ---------------------------------------------------------------------------
#define FUSED_STAGE(AH, AL, BH, BL, cc, buf, LDA)                                 \
    {                                                                             \
        int kk_ = (cc) * 32;                                                      \
        uint32_t d_ = sb + (buf) * 40960;                                         \
        const __nv_bfloat16* ah_ = (AH) + (size_t)m0 * (LDA) + kk_;               \
        const __nv_bfloat16* al_ = (AL) + (size_t)m0 * (LDA) + kk_;               \
        const __nv_bfloat16* bh_ = (BH) + (size_t)n0 * (LDA) + kk_;               \
        const __nv_bfloat16* bl_ = (BL) + (size_t)n0 * (LDA) + kk_;               \
        _Pragma("unroll")                                                         \
        for (int i_ = 0; i_ < 2; ++i_) {                                          \
            int r_ = sr + i_ * 64;                                                \
            uint32_t ro_ = r_ * 80 + sc * 16;                                     \
            size_t go_ = (size_t)r_ * (LDA) + sc * 8;                             \
            cpa16(d_ + ro_, ah_ + go_);                                           \
            cpa16(d_ + 10240 + ro_, al_ + go_);                                   \
            cpa16(d_ + 20480 + ro_, bh_ + go_);                                   \
            cpa16(d_ + 30720 + ro_, bl_ + go_);                                   \
        }                                                                         \
        cpa_commit();                                                             \
    }

#define FUSED_COMPUTE(cc)                                                         \
    {                                                                             \
        uint32_t sA = sb + ((cc) & 1) * 40960, sB = sA + 20480;                   \
        _Pragma("unroll")                                                         \
        for (int kq = 0; kq < 2; ++kq) {                                          \
            uint32_t bh[2][4], bl[2][4];                                          \
            _Pragma("unroll")                                                     \
            for (int nj = 0; nj < 2; ++nj) {                                      \
                ldsm4(bh[nj], sB + bOff + nj * 1280 + kq * 32);                   \
                ldsm4(bl[nj], sB + 10240 + bOff + nj * 1280 + kq * 32);           \
            }                                                                     \
            _Pragma("unroll")                                                     \
            for (int mi = 0; mi < 4; ++mi) {                                      \
                uint32_t ah[4], al[4];                                            \
                ldsm4(ah, sA + aOff + mi * 1280 + kq * 32);                       \
                ldsm4(al, sA + 10240 + aOff + mi * 1280 + kq * 32);               \
                _Pragma("unroll")                                                 \
                for (int nj = 0; nj < 2; ++nj) {                                  \
                    mma16816(acc[mi][nj * 2], ah, bh[nj]);                        \
                    mma16816(acc[mi][nj * 2 + 1], ah, bh[nj] + 2);                \
                    mma16816(acc[mi][nj * 2], ah, bl[nj]);                        \
                    mma16816(acc[mi][nj * 2 + 1], ah, bl[nj] + 2);                \
                    mma16816(acc[mi][nj * 2], al, bh[nj]);                        \
                    mma16816(acc[mi][nj * 2 + 1], al, bh[nj] + 2);                \
                }                                                                 \
            }                                                                     \
        }                                                                         \
    }

// ---------------------------------------------------------------------------
// 2-term fp16 GEMM body (A split hi/lo, B single). Stage per buffer (30720B):
// Ah@0, Al@10240, B@20480.
// ---------------------------------------------------------------------------
#define STAGE2(AH, AL, B, cc, buf, LDA)                                           \
    {                                                                             \
        int kk_ = (cc) * 32;                                                      \
        uint32_t d_ = sb + (buf) * 30720;                                         \
        const __half* ah_ = (AH) + (size_t)m0 * (LDA) + kk_;                      \
        const __half* al_ = (AL) + (size_t)m0 * (LDA) + kk_;                      \
        const __half* b_  = (B)  + (size_t)n0 * (LDA) + kk_;                      \
        _Pragma("unroll")                                                         \
        for (int i_ = 0; i_ < 2; ++i_) {                                          \
            int r_ = sr + i_ * 64;                                                \
            uint32_t ro_ = r_ * 80 + sc * 16;                                     \
            size_t go_ = (size_t)r_ * (LDA) + sc * 8;                             \
            cpa16(d_ + ro_, ah_ + go_);                                           \
            cpa16(d_ + 10240 + ro_, al_ + go_);                                   \
            cpa16(d_ + 20480 + ro_, b_ + go_);                                    \
        }                                                                         \
        cpa_commit();                                                             \
    }

#define COMPUTE2(cc)                                                              \
    {                                                                             \
        uint32_t sA = sb + ((cc) & 1) * 30720, sB = sA + 20480;                   \
        _Pragma("unroll")                                                         \
        for (int kq = 0; kq < 2; ++kq) {                                          \
            uint32_t bh[2][4];                                                    \
            ldsm4(bh[0], sB + bOff + kq * 32);                                    \
            ldsm4(bh[1], sB + bOff + 1280 + kq * 32);                             \
            _Pragma("unroll")                                                     \
            for (int mi = 0; mi < 4; ++mi) {                                      \
                uint32_t ah[4], al[4];                                            \
                ldsm4(ah, sA + aOff + mi * 1280 + kq * 32);                       \
                ldsm4(al, sA + 10240 + aOff + mi * 1280 + kq * 32);               \
                _Pragma("unroll")                                                 \
                for (int nj = 0; nj < 2; ++nj) {                                  \
                    mma_h(acc[mi][nj * 2], ah, bh[nj]);                           \
                    mma_h(acc[mi][nj * 2 + 1], ah, bh[nj] + 2);                   \
                    mma_h(acc[mi][nj * 2], al, bh[nj]);                           \
                    mma_h(acc[mi][nj * 2 + 1], al, bh[nj] + 2);                   \
                }                                                                 \
            }                                                                     \
        }                                                                         \
    }

#define GEMM_PRO()                                                                \
    float acc[4][4][4];                                                           \
    _Pragma("unroll")                                                             \
    for (int mi = 0; mi < 4; ++mi)                                                \
        _Pragma("unroll")                                                         \
        for (int ni = 0; ni < 4; ++ni)                                            \
            _Pragma("unroll")                                                     \
            for (int q = 0; q < 4; ++q) acc[mi][ni][q] = 0.0f;                    \
    const int sr = t >> 2, sc = t & 3;                                            \
    const uint32_t aOff = (uint32_t)(wr * 64 + (lane & 15)) * 80 + (lane >> 4) * 16; \
    const uint32_t bOff = (uint32_t)(wc * 32 + (lane & 7) + ((lane >> 4) & 1) * 8) * 80 + \
                          ((lane >> 3) & 1) * 16;

// ---------------------------------------------------------------------------
// QKV projection (bf16 3-term, fp32-exact). z=0: Q -> fp16 hi/lo. z=1: K -> fp16.
// z=2: V -> fp32.
// ---------------------------------------------------------------------------
__global__ __launch_bounds__(256, 2)
void proj_kernel(const float* __restrict__ bq, const float* __restrict__ bk,
                 const float* __restrict__ bv) {
    extern __shared__ __align__(128) char smem[];
    const int t = threadIdx.x, wid = t >> 5, lane = t & 31;
    const int z = blockIdx.z;
    const int m0 = blockIdx.y * 128, n0 = blockIdx.x * 128;
    const uint32_t sb = smem_u32(smem);
    const int wr = wid >> 2, wc = wid & 3;
    const __nv_bfloat16* WHz = gw_hi + (size_t)z * DD * DD;
    const __nv_bfloat16* WLz = gw_lo + (size_t)z * DD * DD;

    GEMM_PRO();
    FUSED_STAGE(gx_hi, gx_lo, WHz, WLz, 0, 0, DD);
    for (int cc = 0; cc < 16; ++cc) {
        asm volatile("cp.async.wait_group 0;" ::: "memory");
        __syncthreads();
        if (cc < 15) FUSED_STAGE(gx_hi, gx_lo, WHz, WLz, cc + 1, (cc + 1) & 1, DD);
        FUSED_COMPUTE(cc);
    }

    const float* bias = (z == 0) ? bq : (z == 1) ? bk : bv;
#pragma unroll
    for (int mi = 0; mi < 4; ++mi) {
#pragma unroll
        for (int h = 0; h < 2; ++h) {
            int row = m0 + wr * 64 + mi * 16 + (lane >> 2) + h * 8;
#pragma unroll
            for (int ni = 0; ni < 4; ++ni) {
                int col = n0 + wc * 32 + ni * 8 + (lane & 3) * 2;
                float2 bb = *(const float2*)(bias + col);
                float v0 = acc[mi][ni][h * 2] + bb.x;
                float v1 = acc[mi][ni][h * 2 + 1] + bb.y;
                size_t o = (size_t)row * DD + col;
                if (z == 2) {
                    *(float2*)(g_v + o) = make_float2(v0, v1);
                } else if (z == 1) {
                    *(uint32_t*)(gk_h + o) = pack2h(__float2half(v0), __float2half(v1));
                } else {
                    __half h0 = __float2half(v0), h1 = __float2half(v1);
                    *(uint32_t*)(gq_h + o) = pack2h(h0, h1);
                    *(uint32_t*)(gq_l + o) =
                        pack2h(__float2half(v0 - __half2float(h0)),
                               __float2half(v1 - __half2float(h1)));
                }
            }
        }
    }
}

// ---------------------------------------------------------------------------
// V transpose -> fp16: gvt_h[d][j] = fp16(g_v[j][d])
// ---------------------------------------------------------------------------
__global__ __launch_bounds__(256, 4)
void vtrans_kernel() {
    __shared__ float ts[32][33];
    int j0 = blockIdx.x * 32, d0 = blockIdx.y * 32;
    int tx = threadIdx.x & 31, ty = threadIdx.x >> 5;
#pragma unroll
    for (int i = 0; i < 4; ++i)
        ts[ty + 8 * i][tx] = g_v[(size_t)(j0 + ty + 8 * i) * DD + d0 + tx];
    __syncthreads();
#pragma unroll
    for (int i = 0; i < 4; ++i) {
        float v = ts[tx][ty + 8 * i];
        gvt_h[(size_t)(d0 + ty + 8 * i) * NN + j0 + tx] = __float2half(v);
    }
}

// ---------------------------------------------------------------------------
// Pass 1: P = exp(scale*(Qh+Ql)@K^T + sp + ed); store scaled P (fp16 hi/lo),
// per-CTA row-sum partials. 2-term fp16 mainloop.
// ---------------------------------------------------------------------------
__global__ __launch_bounds__(256, 2)
void pass1_kernel(const float* __restrict__ sp, const float* __restrict__ ed) {
    extern __shared__ __align__(128) char smem[];
    float* smem_l = (float*)(smem + 61440);
    const int t = threadIdx.x, wid = t >> 5, lane = t & 31;
    const int m0 = blockIdx.y * 128, n0 = blockIdx.x * 128;
    const uint32_t sb = smem_u32(smem);
    const int wr = wid >> 2, wc = wid & 3;

    GEMM_PRO();
    STAGE2(gq_h, gq_l, gk_h, 0, 0, DD);
    for (int cc = 0; cc < 16; ++cc) {
        asm volatile("cp.async.wait_group 0;" ::: "memory");
        __syncthreads();
        if (cc < 15) STAGE2(gq_h, gq_l, gk_h, cc + 1, (cc + 1) & 1, DD);
        COMPUTE2(cc);
    }

    // epilogue: bias add, exp, split-store scaled P, row sums
#pragma unroll
    for (int mi = 0; mi < 4; ++mi) {
#pragma unroll
        for (int h = 0; h < 2; ++h) {
            int rloc = wr * 64 + mi * 16 + (lane >> 2) + h * 8;
            size_t rb = (size_t)(m0 + rloc) * NN;
            float rs = 0.0f;
#pragma unroll
            for (int ni = 0; ni < 4; ++ni) {
                int col = n0 + wc * 32 + ni * 8 + (lane & 3) * 2;
                float2 s2 = *(const float2*)(sp + rb + col);
                float2 e2 = *(const float2*)(ed + rb + col);
                float p0 = __expf(acc[mi][ni][h * 2] * SCALE + s2.x + e2.x);
                float p1 = __expf(acc[mi][ni][h * 2 + 1] * SCALE + s2.y + e2.y);
                float q0 = p0 * PSC, q1 = p1 * PSC;
                __half h0 = __float2half(q0), h1 = __float2half(q1);
                *(uint32_t*)(gP_h + rb + col) = pack2h(h0, h1);
                *(uint32_t*)(gP_l + rb + col) =
                    pack2h(__float2half(q0 - __half2float(h0)),
                           __float2half(q1 - __half2float(h1)));
                rs += p0 + p1;
            }
            rs += __shfl_xor_sync(0xffffffffu, rs, 1);
            rs += __shfl_xor_sync(0xffffffffu, rs, 2);
            if ((lane & 3) == 0) smem_l[rloc * 4 + wc] = rs;
        }
    }
    __syncthreads();
    if (t < 128) {
        float s = smem_l[t * 4] + smem_l[t * 4 + 1] + smem_l[t * 4 + 2] + smem_l[t * 4 + 3];
        g_lpart[(size_t)blockIdx.x * NN + m0 + t] = s;
    }
}

// ---------------------------------------------------------------------------
// l reduce (deterministic)
// ---------------------------------------------------------------------------
__global__ void lreduce_kernel() {
    int r = blockIdx.x * 256 + threadIdx.x;
    float s = 0.0f;
    for (int b = 0; b < 64; ++b) s += g_lpart[(size_t)b * NN + r];
    g_l[r] = s;
}

// ---------------------------------------------------------------------------
// Pass 2: O = ((Ph+Pl) @ Vh) * 65536 / l. 2-term fp16, CTA 128x128 (m x d),
// K = 8192 in 256 chunks.
// ---------------------------------------------------------------------------
__global__ __launch_bounds__(256, 2)
void pass2_kernel(float* __restrict__ outp) {
    extern __shared__ __align__(128) char smem[];
    const int t = threadIdx.x, wid = t >> 5, lane = t & 31;
    const int n0 = blockIdx.x * 128, m0 = blockIdx.y * 128;
    const uint32_t sb = smem_u32(smem);
    const int wr = wid >> 2, wc = wid & 3;

    GEMM_PRO();
    STAGE2(gP_h, gP_l, gvt_h, 0, 0, NN);
    for (int cc = 0; cc < 256; ++cc) {
        asm volatile("cp.async.wait_group 0;" ::: "memory");
        __syncthreads();
        if (cc < 255) STAGE2(gP_h, gP_l, gvt_h, cc + 1, (cc + 1) & 1, NN);
        COMPUTE2(cc);
    }

    // epilogue: multiply by 65536/l, store
#pragma unroll
    for (int mi = 0; mi < 4; ++mi) {
#pragma unroll
        for (int h = 0; h < 2; ++h) {
            int row = m0 + wr * 64 + mi * 16 + (lane >> 2) + h * 8;
            float inv = PSCI / g_l[row];
#pragma unroll
            for (int ni = 0; ni < 4; ++ni) {
                int col = n0 + wc * 32 + ni * 8 + (lane & 3) * 2;
                float2 o;
                o.x = acc[mi][ni][h * 2] * inv;
                o.y = acc[mi][ni][h * 2 + 1] * inv;
                *(float2*)(outp + (size_t)row * DD + col) = o;
            }
        }
    }
}

// ---------------------------------------------------------------------------
extern "C" void kernel_launch(void* const* d_in, const int* in_sizes, int n_in,
                              void* d_out, int out_size) {
    const float* x       = (const float*)d_in[0];
    const float* spatial = (const float*)d_in[1];
    const float* edge    = (const float*)d_in[2];
    const float* Wq      = (const float*)d_in[3];
    const float* bq      = (const float*)d_in[4];
    const float* Wk      = (const float*)d_in[5];
    const float* bk      = (const float*)d_in[6];
    const float* Wv      = (const float*)d_in[7];
    const float* bv      = (const float*)d_in[8];
    float* out           = (float*)d_out;

    cudaFuncSetAttribute(proj_kernel, cudaFuncAttributeMaxDynamicSharedMemorySize, 81920);
    cudaFuncSetAttribute(pass1_kernel, cudaFuncAttributeMaxDynamicSharedMemorySize, 63488);
    cudaFuncSetAttribute(pass2_kernel, cudaFuncAttributeMaxDynamicSharedMemorySize, 61440);

    split_kernel<<<4864, 256>>>(x, Wq, Wk, Wv);
    proj_kernel<<<dim3(4, 64, 3), 256, 81920>>>(bq, bk, bv);
    vtrans_kernel<<<dim3(NN / 32, DD / 32), 256>>>();
    pass1_kernel<<<dim3(64, 64), 256, 63488>>>(spatial, edge);
    lreduce_kernel<<<32, 256>>>();
    pass2_kernel<<<dim3(4, 64), 256, 61440>>>(out);
}

// round 16
// speedup vs baseline: 2.1277x; 1.4171x over previous
#include <cuda_runtime.h>
#include <cuda_bf16.h>
#include <cuda_fp16.h>
#include <stdint.h>
#include <math.h>

#define NN 8192
#define DD 512
#define SCALE 0.044194173824159216f
#define PSC 1.52587890625e-05f   // 2^-16
#define PSCI 65536.0f

// ----------------- device scratch (allocation-free rule) -----------------
__device__ float g_v[NN * DD];
__device__ __nv_bfloat16 gx_hi[NN * DD], gx_lo[NN * DD];
__device__ __nv_bfloat16 gw_hi[3 * DD * DD], gw_lo[3 * DD * DD];
__device__ __half gq_h[NN * DD];                  // Q fp16
__device__ __half gk_h[NN * DD];                  // K fp16
__device__ __half gvt_h[DD * NN];                 // V^T fp16
__device__ __half gP_h[(size_t)NN * NN];          // scaled P fp16
__device__ float g_lpart[64 * NN];
__device__ float g_l[NN];

// ----------------- helpers -----------------
__device__ __forceinline__ uint32_t smem_u32(const void* p) {
    uint32_t a;
    asm("{ .reg .u64 t; cvta.to.shared.u64 t, %1; cvt.u32.u64 %0, t; }" : "=r"(a) : "l"(p));
    return a;
}
__device__ __forceinline__ uint32_t pack2(__nv_bfloat16 a, __nv_bfloat16 b) {
    return (uint32_t)__bfloat16_as_ushort(a) | ((uint32_t)__bfloat16_as_ushort(b) << 16);
}
__device__ __forceinline__ uint32_t pack2h(__half a, __half b) {
    return (uint32_t)__half_as_ushort(a) | ((uint32_t)__half_as_ushort(b) << 16);
}
__device__ __forceinline__ void cpa16(uint32_t dst, const void* src) {
    asm volatile("cp.async.cg.shared.global [%0], [%1], 16;" :: "r"(dst), "l"(src));
}
__device__ __forceinline__ void cpa_commit() {
    asm volatile("cp.async.commit_group;" ::: "memory");
}
__device__ __forceinline__ void ldsm4(uint32_t* r, uint32_t addr) {
    asm volatile("ldmatrix.sync.aligned.m8n8.x4.shared.b16 {%0,%1,%2,%3}, [%4];"
                 : "=r"(r[0]), "=r"(r[1]), "=r"(r[2]), "=r"(r[3]) : "r"(addr));
}
__device__ __forceinline__ void mma16816(float* c, const uint32_t* a, const uint32_t* b) {
    asm volatile(
        "mma.sync.aligned.m16n8k16.row.col.f32.bf16.bf16.f32 "
        "{%0,%1,%2,%3}, {%4,%5,%6,%7}, {%8,%9}, {%0,%1,%2,%3};"
        : "+f"(c[0]), "+f"(c[1]), "+f"(c[2]), "+f"(c[3])
        : "r"(a[0]), "r"(a[1]), "r"(a[2]), "r"(a[3]), "r"(b[0]), "r"(b[1]));
}
__device__ __forceinline__ void mma_h(float* c, const uint32_t* a, const uint32_t* b) {
    asm volatile(
        "mma.sync.aligned.m16n8k16.row.col.f32.f16.f16.f32 "
        "{%0,%1,%2,%3}, {%4,%5,%6,%7}, {%8,%9}, {%0,%1,%2,%3};"
        : "+f"(c[0]), "+f"(c[1]), "+f"(c[2]), "+f"(c[3])
        : "r"(a[0]), "r"(a[1]), "r"(a[2]), "r"(a[3]), "r"(b[0]), "r"(b[1]));
}

// ---------------------------------------------------------------------------
// Split x and Wq/Wk/Wv into bf16 hi/lo (proj inputs; fp32-accurate 3-term)
// ---------------------------------------------------------------------------
__global__ __launch_bounds__(256)
void split_kernel(const float* __restrict__ x, const float* __restrict__ Wq,
                  const float* __restrict__ Wk, const float* __restrict__ Wv) {
    int i4 = blockIdx.x * 256 + threadIdx.x;
    const float4* src;
    uint2 *oh, *ol;
    int off;
    if (i4 < NN * DD / 4) {
        src = (const float4*)x; oh = (uint2*)gx_hi; ol = (uint2*)gx_lo; off = i4;
    } else {
        int r = i4 - NN * DD / 4;
        int wi = r >> 16, rr = r & 65535;
        const float* w = (wi == 0) ? Wq : (wi == 1) ? Wk : Wv;
        src = (const float4*)w; off = rr;
        oh = (uint2*)(gw_hi + (size_t)wi * DD * DD);
        ol = (uint2*)(gw_lo + (size_t)wi * DD * DD);
    }
    float4 v = src[off];
    __nv_bfloat16 h0 = __float2bfloat16(v.x), h1 = __float2bfloat16(v.y);
    __nv_bfloat16 h2 = __float2bfloat16(v.z), h3 = __float2bfloat16(v.w);
    uint2 H, L;
    H.x = pack2(h0, h1);
    H.y = pack2(h2, h3);
    L.x = pack2(__float2bfloat16(v.x - __bfloat162float(h0)),
                __float2bfloat16(v.y - __bfloat162float(h1)));
    L.y = pack2(__float2bfloat16(v.z - __bfloat162float(h2)),
                __float2bfloat16(v.w - __bfloat162float(h3)));
    oh[off] = H;
    ol[off] = L;
}

// ---------------------------------------------------------------------------
// 3-term bf16 GEMM body for proj (CTA 128x128, warps 2x4, warp 64x32).
// Stage per buffer (40960B): Ah@0, Al@10240, Bh@20480, Bl@30720.
// ---------------------------------------------------------------------------
#define FUSED_STAGE(AH, AL, BH, BL, cc, buf, LDA)                                 \
    {                                                                             \
        int kk_ = (cc) * 32;                                                      \
        uint32_t d_ = sb + (buf) * 40960;                                         \
        const __nv_bfloat16* ah_ = (AH) + (size_t)m0 * (LDA) + kk_;               \
        const __nv_bfloat16* al_ = (AL) + (size_t)m0 * (LDA) + kk_;               \
        const __nv_bfloat16* bh_ = (BH) + (size_t)n0 * (LDA) + kk_;               \
        const __nv_bfloat16* bl_ = (BL) + (size_t)n0 * (LDA) + kk_;               \
        _Pragma("unroll")                                                         \
        for (int i_ = 0; i_ < 2; ++i_) {                                          \
            int r_ = sr + i_ * 64;                                                \
            uint32_t ro_ = r_ * 80 + sc * 16;                                     \
            size_t go_ = (size_t)r_ * (LDA) + sc * 8;                             \
            cpa16(d_ + ro_, ah_ + go_);                                           \
            cpa16(d_ + 10240 + ro_, al_ + go_);                                   \
            cpa16(d_ + 20480 + ro_, bh_ + go_);                                   \
            cpa16(d_ + 30720 + ro_, bl_ + go_);                                   \
        }                                                                         \
        cpa_commit();                                                             \
    }

#define FUSED_COMPUTE(cc)                                                         \
    {                                                                             \
        uint32_t sA = sb + ((cc) & 1) * 40960, sB = sA + 20480;                   \
        _Pragma("unroll")                                                         \
        for (int kq = 0; kq < 2; ++kq) {                                          \
            uint32_t bh[2][4], bl[2][4];                                          \
            _Pragma("unroll")                                                     \
            for (int nj = 0; nj < 2; ++nj) {                                      \
                ldsm4(bh[nj], sB + bOff + nj * 1280 + kq * 32);                   \
                ldsm4(bl[nj], sB + 10240 + bOff + nj * 1280 + kq * 32);           \
            }                                                                     \
            _Pragma("unroll")                                                     \
            for (int mi = 0; mi < 4; ++mi) {                                      \
                uint32_t ah[4], al[4];                                            \
                ldsm4(ah, sA + aOff + mi * 1280 + kq * 32);                       \
                ldsm4(al, sA + 10240 + aOff + mi * 1280 + kq * 32);               \
                _Pragma("unroll")                                                 \
                for (int nj = 0; nj < 2; ++nj) {                                  \
                    mma16816(acc[mi][nj * 2], ah, bh[nj]);                        \
                    mma16816(acc[mi][nj * 2 + 1], ah, bh[nj] + 2);                \
                    mma16816(acc[mi][nj * 2], ah, bl[nj]);                        \
                    mma16816(acc[mi][nj * 2 + 1], ah, bl[nj] + 2);                \
                    mma16816(acc[mi][nj * 2], al, bh[nj]);                        \
                    mma16816(acc[mi][nj * 2 + 1], al, bh[nj] + 2);                \
                }                                                                 \
            }                                                                     \
        }                                                                         \
    }

// ---------------------------------------------------------------------------
// 1-term fp16 GEMM body (A single, B single). Stage per buffer (20480B):
// A@0, B@10240.
// ---------------------------------------------------------------------------
#define STAGE1(A, B, cc, buf, LDA)                                                \
    {                                                                             \
        int kk_ = (cc) * 32;                                                      \
        uint32_t d_ = sb + (buf) * 20480;                                         \
        const __half* a_ = (A) + (size_t)m0 * (LDA) + kk_;                        \
        const __half* b_ = (B) + (size_t)n0 * (LDA) + kk_;                        \
        _Pragma("unroll")                                                         \
        for (int i_ = 0; i_ < 2; ++i_) {                                          \
            int r_ = sr + i_ * 64;                                                \
            uint32_t ro_ = r_ * 80 + sc * 16;                                     \
            size_t go_ = (size_t)r_ * (LDA) + sc * 8;                             \
            cpa16(d_ + ro_, a_ + go_);                                            \
            cpa16(d_ + 10240 + ro_, b_ + go_);                                    \
        }                                                                         \
        cpa_commit();                                                             \
    }

#define COMPUTE1(cc)                                                              \
    {                                                                             \
        uint32_t sA = sb + ((cc) & 1) * 20480, sB = sA + 10240;                   \
        _Pragma("unroll")                                                         \
        for (int kq = 0; kq < 2; ++kq) {                                          \
            uint32_t bh[2][4];                                                    \
            ldsm4(bh[0], sB + bOff + kq * 32);                                    \
            ldsm4(bh[1], sB + bOff + 1280 + kq * 32);                             \
            _Pragma("unroll")                                                     \
            for (int mi = 0; mi < 4; ++mi) {                                      \
                uint32_t a[4];                                                    \
                ldsm4(a, sA + aOff + mi * 1280 + kq * 32);                        \
                _Pragma("unroll")                                                 \
                for (int nj = 0; nj < 2; ++nj) {                                  \
                    mma_h(acc[mi][nj * 2], a, bh[nj]);                            \
                    mma_h(acc[mi][nj * 2 + 1], a, bh[nj] + 2);                    \
                }                                                                 \
            }                                                                     \
        }                                                                         \
    }

#define GEMM_PRO()                                                                \
    float acc[4][4][4];                                                           \
    _Pragma("unroll")                                                             \
    for (int mi = 0; mi < 4; ++mi)                                                \
        _Pragma("unroll")                                                         \
        for (int ni = 0; ni < 4; ++ni)                                            \
            _Pragma("unroll")                                                     \
            for (int q = 0; q < 4; ++q) acc[mi][ni][q] = 0.0f;                    \
    const int sr = t >> 2, sc = t & 3;                                            \
    const uint32_t aOff = (uint32_t)(wr * 64 + (lane & 15)) * 80 + (lane >> 4) * 16; \
    const uint32_t bOff = (uint32_t)(wc * 32 + (lane & 7) + ((lane >> 4) & 1) * 8) * 80 + \
                          ((lane >> 3) & 1) * 16;

// ---------------------------------------------------------------------------
// QKV projection (bf16 3-term, fp32-exact). z=0: Q -> fp16. z=1: K -> fp16.
// z=2: V -> fp32.
// ---------------------------------------------------------------------------
__global__ __launch_bounds__(256, 2)
void proj_kernel(const float* __restrict__ bq, const float* __restrict__ bk,
                 const float* __restrict__ bv) {
    extern __shared__ __align__(128) char smem[];
    const int t = threadIdx.x, wid = t >> 5, lane = t & 31;
    const int z = blockIdx.z;
    const int m0 = blockIdx.y * 128, n0 = blockIdx.x * 128;
    const uint32_t sb = smem_u32(smem);
    const int wr = wid >> 2, wc = wid & 3;
    const __nv_bfloat16* WHz = gw_hi + (size_t)z * DD * DD;
    const __nv_bfloat16* WLz = gw_lo + (size_t)z * DD * DD;

    GEMM_PRO();
    FUSED_STAGE(gx_hi, gx_lo, WHz, WLz, 0, 0, DD);
    for (int cc = 0; cc < 16; ++cc) {
        asm volatile("cp.async.wait_group 0;" ::: "memory");
        __syncthreads();
        if (cc < 15) FUSED_STAGE(gx_hi, gx_lo, WHz, WLz, cc + 1, (cc + 1) & 1, DD);
        FUSED_COMPUTE(cc);
    }

    const float* bias = (z == 0) ? bq : (z == 1) ? bk : bv;
#pragma unroll
    for (int mi = 0; mi < 4; ++mi) {
#pragma unroll
        for (int h = 0; h < 2; ++h) {
            int row = m0 + wr * 64 + mi * 16 + (lane >> 2) + h * 8;
#pragma unroll
            for (int ni = 0; ni < 4; ++ni) {
                int col = n0 + wc * 32 + ni * 8 + (lane & 3) * 2;
                float2 bb = *(const float2*)(bias + col);
                float v0 = acc[mi][ni][h * 2] + bb.x;
                float v1 = acc[mi][ni][h * 2 + 1] + bb.y;
                size_t o = (size_t)row * DD + col;
                if (z == 2) {
                    *(float2*)(g_v + o) = make_float2(v0, v1);
                } else {
                    __half* dst = (z == 1) ? gk_h : gq_h;
                    *(uint32_t*)(dst + o) = pack2h(__float2half(v0), __float2half(v1));
                }
            }
        }
    }
}

// ---------------------------------------------------------------------------
// V transpose -> fp16: gvt_h[d][j] = fp16(g_v[j][d])
// ---------------------------------------------------------------------------
__global__ __launch_bounds__(256, 4)
void vtrans_kernel() {
    __shared__ float ts[32][33];
    int j0 = blockIdx.x * 32, d0 = blockIdx.y * 32;
    int tx = threadIdx.x & 31, ty = threadIdx.x >> 5;
#pragma unroll
    for (int i = 0; i < 4; ++i)
        ts[ty + 8 * i][tx] = g_v[(size_t)(j0 + ty + 8 * i) * DD + d0 + tx];
    __syncthreads();
#pragma unroll
    for (int i = 0; i < 4; ++i) {
        float v = ts[tx][ty + 8 * i];
        gvt_h[(size_t)(d0 + ty + 8 * i) * NN + j0 + tx] = __float2half(v);
    }
}

// ---------------------------------------------------------------------------
// Pass 1: P = exp(scale*Q@K^T + sp + ed); store scaled P (fp16),
// per-CTA row-sum partials. 1-term fp16 mainloop.
// ---------------------------------------------------------------------------
__global__ __launch_bounds__(256, 2)
void pass1_kernel(const float* __restrict__ sp, const float* __restrict__ ed) {
    extern __shared__ __align__(128) char smem[];
    float* smem_l = (float*)(smem + 40960);
    const int t = threadIdx.x, wid = t >> 5, lane = t & 31;
    const int m0 = blockIdx.y * 128, n0 = blockIdx.x * 128;
    const uint32_t sb = smem_u32(smem);
    const int wr = wid >> 2, wc = wid & 3;

    GEMM_PRO();
    STAGE1(gq_h, gk_h, 0, 0, DD);
    for (int cc = 0; cc < 16; ++cc) {
        asm volatile("cp.async.wait_group 0;" ::: "memory");
        __syncthreads();
        if (cc < 15) STAGE1(gq_h, gk_h, cc + 1, (cc + 1) & 1, DD);
        COMPUTE1(cc);
    }

    // epilogue: bias add, exp, store scaled P (fp16), row sums
#pragma unroll
    for (int mi = 0; mi < 4; ++mi) {
#pragma unroll
        for (int h = 0; h < 2; ++h) {
            int rloc = wr * 64 + mi * 16 + (lane >> 2) + h * 8;
            size_t rb = (size_t)(m0 + rloc) * NN;
            float rs = 0.0f;
#pragma unroll
            for (int ni = 0; ni < 4; ++ni) {
                int col = n0 + wc * 32 + ni * 8 + (lane & 3) * 2;
                float2 s2 = *(const float2*)(sp + rb + col);
                float2 e2 = *(const float2*)(ed + rb + col);
                float p0 = __expf(acc[mi][ni][h * 2] * SCALE + s2.x + e2.x);
                float p1 = __expf(acc[mi][ni][h * 2 + 1] * SCALE + s2.y + e2.y);
                *(uint32_t*)(gP_h + rb + col) =
                    pack2h(__float2half(p0 * PSC), __float2half(p1 * PSC));
                rs += p0 + p1;
            }
            rs += __shfl_xor_sync(0xffffffffu, rs, 1);
            rs += __shfl_xor_sync(0xffffffffu, rs, 2);
            if ((lane & 3) == 0) smem_l[rloc * 4 + wc] = rs;
        }
    }
    __syncthreads();
    if (t < 128) {
        float s = smem_l[t * 4] + smem_l[t * 4 + 1] + smem_l[t * 4 + 2] + smem_l[t * 4 + 3];
        g_lpart[(size_t)blockIdx.x * NN + m0 + t] = s;
    }
}

// ---------------------------------------------------------------------------
// l reduce (deterministic)
// ---------------------------------------------------------------------------
__global__ void lreduce_kernel() {
    int r = blockIdx.x * 256 + threadIdx.x;
    float s = 0.0f;
    for (int b = 0; b < 64; ++b) s += g_lpart[(size_t)b * NN + r];
    g_l[r] = s;
}

// ---------------------------------------------------------------------------
// Pass 2: O = (P @ Vh) * 65536 / l. 1-term fp16, CTA 128x128 (m x d),
// K = 8192 in 256 chunks.
// ---------------------------------------------------------------------------
__global__ __launch_bounds__(256, 2)
void pass2_kernel(float* __restrict__ outp) {
    extern __shared__ __align__(128) char smem[];
    const int t = threadIdx.x, wid = t >> 5, lane = t & 31;
    const int n0 = blockIdx.x * 128, m0 = blockIdx.y * 128;
    const uint32_t sb = smem_u32(smem);
    const int wr = wid >> 2, wc = wid & 3;

    GEMM_PRO();
    STAGE1(gP_h, gvt_h, 0, 0, NN);
    for (int cc = 0; cc < 256; ++cc) {
        asm volatile("cp.async.wait_group 0;" ::: "memory");
        __syncthreads();
        if (cc < 255) STAGE1(gP_h, gvt_h, cc + 1, (cc + 1) & 1, NN);
        COMPUTE1(cc);
    }

    // epilogue: multiply by 65536/l, store
#pragma unroll
    for (int mi = 0; mi < 4; ++mi) {
#pragma unroll
        for (int h = 0; h < 2; ++h) {
            int row = m0 + wr * 64 + mi * 16 + (lane >> 2) + h * 8;
            float inv = PSCI / g_l[row];
#pragma unroll
            for (int ni = 0; ni < 4; ++ni) {
                int col = n0 + wc * 32 + ni * 8 + (lane & 3) * 2;
                float2 o;
                o.x = acc[mi][ni][h * 2] * inv;
                o.y = acc[mi][ni][h * 2 + 1] * inv;
                *(float2*)(outp + (size_t)row * DD + col) = o;
            }
        }
    }
}

// ---------------------------------------------------------------------------
extern "C" void kernel_launch(void* const* d_in, const int* in_sizes, int n_in,
                              void* d_out, int out_size) {
    const float* x       = (const float*)d_in[0];
    const float* spatial = (const float*)d_in[1];
    const float* edge    = (const float*)d_in[2];
    const float* Wq      = (const float*)d_in[3];
    const float* bq      = (const float*)d_in[4];
    const float* Wk      = (const float*)d_in[5];
    const float* bk      = (const float*)d_in[6];
    const float* Wv      = (const float*)d_in[7];
    const float* bv      = (const float*)d_in[8];
    float* out           = (float*)d_out;

    cudaFuncSetAttribute(proj_kernel, cudaFuncAttributeMaxDynamicSharedMemorySize, 81920);
    cudaFuncSetAttribute(pass1_kernel, cudaFuncAttributeMaxDynamicSharedMemorySize, 43008);
    cudaFuncSetAttribute(pass2_kernel, cudaFuncAttributeMaxDynamicSharedMemorySize, 40960);

    split_kernel<<<4864, 256>>>(x, Wq, Wk, Wv);
    proj_kernel<<<dim3(4, 64, 3), 256, 81920>>>(bq, bk, bv);
    vtrans_kernel<<<dim3(NN / 32, DD / 32), 256>>>();
    pass1_kernel<<<dim3(64, 64), 256, 43008>>>(spatial, edge);
    lreduce_kernel<<<32, 256>>>();
    pass2_kernel<<<dim3(4, 64), 256, 40960>>>(out);
}

// round 17
// speedup vs baseline: 2.3730x; 1.1153x over previous
#include <cuda_runtime.h>
#include <cuda_bf16.h>
#include <cuda_fp16.h>
#include <stdint.h>
#include <math.h>

#define NN 8192
#define DD 512
#define SCALE 0.044194173824159216f
#define PSC 1.52587890625e-05f   // 2^-16
#define PSCI 65536.0f

// ----------------- device scratch (allocation-free rule) -----------------
__device__ float g_v[NN * DD];
__device__ __nv_bfloat16 gx_hi[NN * DD], gx_lo[NN * DD];
__device__ __nv_bfloat16 gw_hi[3 * DD * DD], gw_lo[3 * DD * DD];
__device__ __half gq_h[NN * DD];                  // Q fp16
__device__ __half gk_h[NN * DD];                  // K fp16
__device__ __half gvt_h[DD * NN];                 // V^T fp16
__device__ __half gP_h[(size_t)NN * NN];          // scaled P fp16
__device__ float g_lpart[64 * NN];
__device__ float g_l[NN];

// ----------------- helpers -----------------
__device__ __forceinline__ uint32_t smem_u32(const void* p) {
    uint32_t a;
    asm("{ .reg .u64 t; cvta.to.shared.u64 t, %1; cvt.u32.u64 %0, t; }" : "=r"(a) : "l"(p));
    return a;
}
__device__ __forceinline__ uint32_t pack2(__nv_bfloat16 a, __nv_bfloat16 b) {
    return (uint32_t)__bfloat16_as_ushort(a) | ((uint32_t)__bfloat16_as_ushort(b) << 16);
}
__device__ __forceinline__ uint32_t pack2h(__half a, __half b) {
    return (uint32_t)__half_as_ushort(a) | ((uint32_t)__half_as_ushort(b) << 16);
}
__device__ __forceinline__ void cpa16(uint32_t dst, const void* src) {
    asm volatile("cp.async.cg.shared.global [%0], [%1], 16;" :: "r"(dst), "l"(src));
}
__device__ __forceinline__ void cpa_commit() {
    asm volatile("cp.async.commit_group;" ::: "memory");
}
__device__ __forceinline__ void ldsm4(uint32_t* r, uint32_t addr) {
    asm volatile("ldmatrix.sync.aligned.m8n8.x4.shared.b16 {%0,%1,%2,%3}, [%4];"
                 : "=r"(r[0]), "=r"(r[1]), "=r"(r[2]), "=r"(r[3]) : "r"(addr));
}
__device__ __forceinline__ void mma16816(float* c, const uint32_t* a, const uint32_t* b) {
    asm volatile(
        "mma.sync.aligned.m16n8k16.row.col.f32.bf16.bf16.f32 "
        "{%0,%1,%2,%3}, {%4,%5,%6,%7}, {%8,%9}, {%0,%1,%2,%3};"
        : "+f"(c[0]), "+f"(c[1]), "+f"(c[2]), "+f"(c[3])
        : "r"(a[0]), "r"(a[1]), "r"(a[2]), "r"(a[3]), "r"(b[0]), "r"(b[1]));
}
__device__ __forceinline__ void mma_h(float* c, const uint32_t* a, const uint32_t* b) {
    asm volatile(
        "mma.sync.aligned.m16n8k16.row.col.f32.f16.f16.f32 "
        "{%0,%1,%2,%3}, {%4,%5,%6,%7}, {%8,%9}, {%0,%1,%2,%3};"
        : "+f"(c[0]), "+f"(c[1]), "+f"(c[2]), "+f"(c[3])
        : "r"(a[0]), "r"(a[1]), "r"(a[2]), "r"(a[3]), "r"(b[0]), "r"(b[1]));
}

// ---------------------------------------------------------------------------
// Split x and Wq/Wk/Wv into bf16 hi/lo (proj inputs; fp32-accurate 3-term)
// ---------------------------------------------------------------------------
__global__ __launch_bounds__(256)
void split_kernel(const float* __restrict__ x, const float* __restrict__ Wq,
                  const float* __restrict__ Wk, const float* __restrict__ Wv) {
    int i4 = blockIdx.x * 256 + threadIdx.x;
    const float4* src;
    uint2 *oh, *ol;
    int off;
    if (i4 < NN * DD / 4) {
        src = (const float4*)x; oh = (uint2*)gx_hi; ol = (uint2*)gx_lo; off = i4;
    } else {
        int r = i4 - NN * DD / 4;
        int wi = r >> 16, rr = r & 65535;
        const float* w = (wi == 0) ? Wq : (wi == 1) ? Wk : Wv;
        src = (const float4*)w; off = rr;
        oh = (uint2*)(gw_hi + (size_t)wi * DD * DD);
        ol = (uint2*)(gw_lo + (size_t)wi * DD * DD);
    }
    float4 v = src[off];
    __nv_bfloat16 h0 = __float2bfloat16(v.x), h1 = __float2bfloat16(v.y);
    __nv_bfloat16 h2 = __float2bfloat16(v.z), h3 = __float2bfloat16(v.w);
    uint2 H, L;
    H.x = pack2(h0, h1);
    H.y = pack2(h2, h3);
    L.x = pack2(__float2bfloat16(v.x - __bfloat162float(h0)),
                __float2bfloat16(v.y - __bfloat162float(h1)));
    L.y = pack2(__float2bfloat16(v.z - __bfloat162float(h2)),
                __float2bfloat16(v.w - __bfloat162float(h3)));
    oh[off] = H;
    ol[off] = L;
}

// ---------------------------------------------------------------------------
// 3-term bf16 GEMM body for proj (CTA 128x128, warps 2x4, warp 64x32).
// Stage per buffer (40960B): Ah@0, Al@10240, Bh@20480, Bl@30720. (R15-proven)
// ---------------------------------------------------------------------------
#define FUSED_STAGE(AH, AL, BH, BL, cc, buf, LDA)                                 \
    {                                                                             \
        int kk_ = (cc) * 32;                                                      \
        uint32_t d_ = sb + (buf) * 40960;                                         \
        const __nv_bfloat16* ah_ = (AH) + (size_t)m0 * (LDA) + kk_;               \
        const __nv_bfloat16* al_ = (AL) + (size_t)m0 * (LDA) + kk_;               \
        const __nv_bfloat16* bh_ = (BH) + (size_t)n0 * (LDA) + kk_;               \
        const __nv_bfloat16* bl_ = (BL) + (size_t)n0 * (LDA) + kk_;               \
        _Pragma("unroll")                                                         \
        for (int i_ = 0; i_ < 2; ++i_) {                                          \
            int r_ = sr + i_ * 64;                                                \
            uint32_t ro_ = r_ * 80 + sc * 16;                                     \
            size_t go_ = (size_t)r_ * (LDA) + sc * 8;                             \
            cpa16(d_ + ro_, ah_ + go_);                                           \
            cpa16(d_ + 10240 + ro_, al_ + go_);                                   \
            cpa16(d_ + 20480 + ro_, bh_ + go_);                                   \
            cpa16(d_ + 30720 + ro_, bl_ + go_);                                   \
        }                                                                         \
        cpa_commit();                                                             \
    }

#define FUSED_COMPUTE(cc)                                                         \
    {                                                                             \
        uint32_t sA = sb + ((cc) & 1) * 40960, sB = sA + 20480;                   \
        _Pragma("unroll")                                                         \
        for (int kq = 0; kq < 2; ++kq) {                                          \
            uint32_t bh[2][4], bl[2][4];                                          \
            _Pragma("unroll")                                                     \
            for (int nj = 0; nj < 2; ++nj) {                                      \
                ldsm4(bh[nj], sB + bOff + nj * 1280 + kq * 32);                   \
                ldsm4(bl[nj], sB + 10240 + bOff + nj * 1280 + kq * 32);           \
            }                                                                     \
            _Pragma("unroll")                                                     \
            for (int mi = 0; mi < 4; ++mi) {                                      \
                uint32_t ah[4], al[4];                                            \
                ldsm4(ah, sA + aOff + mi * 1280 + kq * 32);                       \
                ldsm4(al, sA + 10240 + aOff + mi * 1280 + kq * 32);               \
                _Pragma("unroll")                                                 \
                for (int nj = 0; nj < 2; ++nj) {                                  \
                    mma16816(acc[mi][nj * 2], ah, bh[nj]);                        \
                    mma16816(acc[mi][nj * 2 + 1], ah, bh[nj] + 2);                \
                    mma16816(acc[mi][nj * 2], ah, bl[nj]);                        \
                    mma16816(acc[mi][nj * 2 + 1], ah, bl[nj] + 2);                \
                    mma16816(acc[mi][nj * 2], al, bh[nj]);                        \
                    mma16816(acc[mi][nj * 2 + 1], al, bh[nj] + 2);                \
                }                                                                 \
            }                                                                     \
        }                                                                         \
    }

// ---------------------------------------------------------------------------
// 1-term fp16 GEMM body, K-chunk 64, row stride 144B (full-line global reads).
// Stage per buffer (36864B): A@0 (128x144), B@18432.
// ---------------------------------------------------------------------------
#define STG64 36864

#define STAGE64(A, B, cc, buf, LDA)                                               \
    {                                                                             \
        int kk_ = (cc) * 64;                                                      \
        uint32_t d_ = sb + (buf) * STG64;                                         \
        const __half* a_ = (A) + (size_t)m0 * (LDA) + kk_;                        \
        const __half* b_ = (B) + (size_t)n0 * (LDA) + kk_;                        \
        _Pragma("unroll")                                                         \
        for (int i_ = 0; i_ < 4; ++i_) {                                          \
            int idx_ = t + i_ * 256;                                              \
            int r_ = idx_ >> 3, ch_ = idx_ & 7;                                   \
            uint32_t ro_ = r_ * 144 + ch_ * 16;                                   \
            size_t go_ = (size_t)r_ * (LDA) + ch_ * 8;                            \
            cpa16(d_ + ro_, a_ + go_);                                            \
            cpa16(d_ + 18432 + ro_, b_ + go_);                                    \
        }                                                                         \
        cpa_commit();                                                             \
    }

#define COMPUTE64(cc)                                                             \
    {                                                                             \
        uint32_t sA = sb + ((cc) & 1) * STG64, sB = sA + 18432;                   \
        _Pragma("unroll")                                                         \
        for (int s = 0; s < 4; ++s) {                                             \
            uint32_t bh[2][4];                                                    \
            ldsm4(bh[0], sB + bOff + s * 32);                                     \
            ldsm4(bh[1], sB + bOff + 2304 + s * 32);                              \
            _Pragma("unroll")                                                     \
            for (int mi = 0; mi < 4; ++mi) {                                      \
                uint32_t a[4];                                                    \
                ldsm4(a, sA + aOff + mi * 2304 + s * 32);                         \
                _Pragma("unroll")                                                 \
                for (int nj = 0; nj < 2; ++nj) {                                  \
                    mma_h(acc[mi][nj * 2], a, bh[nj]);                            \
                    mma_h(acc[mi][nj * 2 + 1], a, bh[nj] + 2);                    \
                }                                                                 \
            }                                                                     \
        }                                                                         \
    }

#define ACC_INIT()                                                                \
    float acc[4][4][4];                                                           \
    _Pragma("unroll")                                                             \
    for (int mi = 0; mi < 4; ++mi)                                                \
        _Pragma("unroll")                                                         \
        for (int ni = 0; ni < 4; ++ni)                                            \
            _Pragma("unroll")                                                     \
            for (int q = 0; q < 4; ++q) acc[mi][ni][q] = 0.0f;

// 80B-stride fragment offsets (proj)
#define PRO80()                                                                   \
    ACC_INIT();                                                                   \
    const int sr = t >> 2, sc = t & 3;                                            \
    const uint32_t aOff = (uint32_t)(wr * 64 + (lane & 15)) * 80 + (lane >> 4) * 16; \
    const uint32_t bOff = (uint32_t)(wc * 32 + (lane & 7) + ((lane >> 4) & 1) * 8) * 80 + \
                          ((lane >> 3) & 1) * 16;

// 144B-stride fragment offsets (pass1/pass2)
#define PRO144()                                                                  \
    ACC_INIT();                                                                   \
    const uint32_t aOff = (uint32_t)(wr * 64 + (lane & 15)) * 144 + (lane >> 4) * 16; \
    const uint32_t bOff = (uint32_t)(wc * 32 + (lane & 7) + ((lane >> 4) & 1) * 8) * 144 + \
                          ((lane >> 3) & 1) * 16;

// ---------------------------------------------------------------------------
// QKV projection (bf16 3-term, fp32-exact). z=0: Q -> fp16. z=1: K -> fp16.
// z=2: V -> fp32.
// ---------------------------------------------------------------------------
__global__ __launch_bounds__(256, 2)
void proj_kernel(const float* __restrict__ bq, const float* __restrict__ bk,
                 const float* __restrict__ bv) {
    extern __shared__ __align__(128) char smem[];
    const int t = threadIdx.x, wid = t >> 5, lane = t & 31;
    const int z = blockIdx.z;
    const int m0 = blockIdx.y * 128, n0 = blockIdx.x * 128;
    const uint32_t sb = smem_u32(smem);
    const int wr = wid >> 2, wc = wid & 3;
    const __nv_bfloat16* WHz = gw_hi + (size_t)z * DD * DD;
    const __nv_bfloat16* WLz = gw_lo + (size_t)z * DD * DD;

    PRO80();
    FUSED_STAGE(gx_hi, gx_lo, WHz, WLz, 0, 0, DD);
    for (int cc = 0; cc < 16; ++cc) {
        asm volatile("cp.async.wait_group 0;" ::: "memory");
        __syncthreads();
        if (cc < 15) FUSED_STAGE(gx_hi, gx_lo, WHz, WLz, cc + 1, (cc + 1) & 1, DD);
        FUSED_COMPUTE(cc);
    }

    const float* bias = (z == 0) ? bq : (z == 1) ? bk : bv;
#pragma unroll
    for (int mi = 0; mi < 4; ++mi) {
#pragma unroll
        for (int h = 0; h < 2; ++h) {
            int row = m0 + wr * 64 + mi * 16 + (lane >> 2) + h * 8;
#pragma unroll
            for (int ni = 0; ni < 4; ++ni) {
                int col = n0 + wc * 32 + ni * 8 + (lane & 3) * 2;
                float2 bb = *(const float2*)(bias + col);
                float v0 = acc[mi][ni][h * 2] + bb.x;
                float v1 = acc[mi][ni][h * 2 + 1] + bb.y;
                size_t o = (size_t)row * DD + col;
                if (z == 2) {
                    *(float2*)(g_v + o) = make_float2(v0, v1);
                } else {
                    __half* dst = (z == 1) ? gk_h : gq_h;
                    *(uint32_t*)(dst + o) = pack2h(__float2half(v0), __float2half(v1));
                }
            }
        }
    }
}

// ---------------------------------------------------------------------------
// V transpose -> fp16: gvt_h[d][j] = fp16(g_v[j][d])
// ---------------------------------------------------------------------------
__global__ __launch_bounds__(256, 4)
void vtrans_kernel() {
    __shared__ float ts[32][33];
    int j0 = blockIdx.x * 32, d0 = blockIdx.y * 32;
    int tx = threadIdx.x & 31, ty = threadIdx.x >> 5;
#pragma unroll
    for (int i = 0; i < 4; ++i)
        ts[ty + 8 * i][tx] = g_v[(size_t)(j0 + ty + 8 * i) * DD + d0 + tx];
    __syncthreads();
#pragma unroll
    for (int i = 0; i < 4; ++i) {
        float v = ts[tx][ty + 8 * i];
        gvt_h[(size_t)(d0 + ty + 8 * i) * NN + j0 + tx] = __float2half(v);
    }
}

// ---------------------------------------------------------------------------
// Pass 1: P = exp(scale*Q@K^T + sp + ed); store scaled P (fp16),
// per-CTA row-sum partials. 1-term fp16, K-chunk 64.
// ---------------------------------------------------------------------------
__global__ __launch_bounds__(256, 2)
void pass1_kernel(const float* __restrict__ sp, const float* __restrict__ ed) {
    extern __shared__ __align__(128) char smem[];
    float* smem_l = (float*)(smem + 2 * STG64);
    const int t = threadIdx.x, wid = t >> 5, lane = t & 31;
    const int m0 = blockIdx.y * 128, n0 = blockIdx.x * 128;
    const uint32_t sb = smem_u32(smem);
    const int wr = wid >> 2, wc = wid & 3;

    PRO144();
    STAGE64(gq_h, gk_h, 0, 0, DD);
    for (int cc = 0; cc < 8; ++cc) {
        asm volatile("cp.async.wait_group 0;" ::: "memory");
        __syncthreads();
        if (cc < 7) STAGE64(gq_h, gk_h, cc + 1, (cc + 1) & 1, DD);
        COMPUTE64(cc);
    }

    // epilogue: bias add, exp, store scaled P (fp16), row sums
#pragma unroll
    for (int mi = 0; mi < 4; ++mi) {
#pragma unroll
        for (int h = 0; h < 2; ++h) {
            int rloc = wr * 64 + mi * 16 + (lane >> 2) + h * 8;
            size_t rb = (size_t)(m0 + rloc) * NN;
            float rs = 0.0f;
#pragma unroll
            for (int ni = 0; ni < 4; ++ni) {
                int col = n0 + wc * 32 + ni * 8 + (lane & 3) * 2;
                float2 s2 = *(const float2*)(sp + rb + col);
                float2 e2 = *(const float2*)(ed + rb + col);
                float p0 = __expf(acc[mi][ni][h * 2] * SCALE + s2.x + e2.x);
                float p1 = __expf(acc[mi][ni][h * 2 + 1] * SCALE + s2.y + e2.y);
                *(uint32_t*)(gP_h + rb + col) =
                    pack2h(__float2half(p0 * PSC), __float2half(p1 * PSC));
                rs += p0 + p1;
            }
            rs += __shfl_xor_sync(0xffffffffu, rs, 1);
            rs += __shfl_xor_sync(0xffffffffu, rs, 2);
            if ((lane & 3) == 0) smem_l[rloc * 4 + wc] = rs;
        }
    }
    __syncthreads();
    if (t < 128) {
        float s = smem_l[t * 4] + smem_l[t * 4 + 1] + smem_l[t * 4 + 2] + smem_l[t * 4 + 3];
        g_lpart[(size_t)blockIdx.x * NN + m0 + t] = s;
    }
}

// ---------------------------------------------------------------------------
// l reduce (deterministic)
// ---------------------------------------------------------------------------
__global__ void lreduce_kernel() {
    int r = blockIdx.x * 256 + threadIdx.x;
    float s = 0.0f;
    for (int b = 0; b < 64; ++b) s += g_lpart[(size_t)b * NN + r];
    g_l[r] = s;
}

// ---------------------------------------------------------------------------
// Pass 2: O = (P @ Vh) * 65536 / l. 1-term fp16, K-chunk 64, CTA 128x128 (m x d),
// K = 8192 in 128 chunks.
// ---------------------------------------------------------------------------
__global__ __launch_bounds__(256, 2)
void pass2_kernel(float* __restrict__ outp) {
    extern __shared__ __align__(128) char smem[];
    const int t = threadIdx.x, wid = t >> 5, lane = t & 31;
    const int n0 = blockIdx.x * 128, m0 = blockIdx.y * 128;
    const uint32_t sb = smem_u32(smem);
    const int wr = wid >> 2, wc = wid & 3;

    PRO144();
    STAGE64(gP_h, gvt_h, 0, 0, NN);
    for (int cc = 0; cc < 128; ++cc) {
        asm volatile("cp.async.wait_group 0;" ::: "memory");
        __syncthreads();
        if (cc < 127) STAGE64(gP_h, gvt_h, cc + 1, (cc + 1) & 1, NN);
        COMPUTE64(cc);
    }

    // epilogue: multiply by 65536/l, store
#pragma unroll
    for (int mi = 0; mi < 4; ++mi) {
#pragma unroll
        for (int h = 0; h < 2; ++h) {
            int row = m0 + wr * 64 + mi * 16 + (lane >> 2) + h * 8;
            float inv = PSCI / g_l[row];
#pragma unroll
            for (int ni = 0; ni < 4; ++ni) {
                int col = n0 + wc * 32 + ni * 8 + (lane & 3) * 2;
                float2 o;
                o.x = acc[mi][ni][h * 2] * inv;
                o.y = acc[mi][ni][h * 2 + 1] * inv;
                *(float2*)(outp + (size_t)row * DD + col) = o;
            }
        }
    }
}

// ---------------------------------------------------------------------------
extern "C" void kernel_launch(void* const* d_in, const int* in_sizes, int n_in,
                              void* d_out, int out_size) {
    const float* x       = (const float*)d_in[0];
    const float* spatial = (const float*)d_in[1];
    const float* edge    = (const float*)d_in[2];
    const float* Wq      = (const float*)d_in[3];
    const float* bq      = (const float*)d_in[4];
    const float* Wk      = (const float*)d_in[5];
    const float* bk      = (const float*)d_in[6];
    const float* Wv      = (const float*)d_in[7];
    const float* bv      = (const float*)d_in[8];
    float* out           = (float*)d_out;

    cudaFuncSetAttribute(proj_kernel, cudaFuncAttributeMaxDynamicSharedMemorySize, 81920);
    cudaFuncSetAttribute(pass1_kernel, cudaFuncAttributeMaxDynamicSharedMemorySize, 2 * STG64 + 2048);
    cudaFuncSetAttribute(pass2_kernel, cudaFuncAttributeMaxDynamicSharedMemorySize, 2 * STG64);

    split_kernel<<<4864, 256>>>(x, Wq, Wk, Wv);
    proj_kernel<<<dim3(4, 64, 3), 256, 81920>>>(bq, bk, bv);
    vtrans_kernel<<<dim3(NN / 32, DD / 32), 256>>>();
    pass1_kernel<<<dim3(64, 64), 256, 2 * STG64 + 2048>>>(spatial, edge);
    lreduce_kernel<<<32, 256>>>();
    pass2_kernel<<<dim3(4, 64), 256, 2 * STG64>>>(out);
}